// round 10
// baseline (speedup 1.0000x reference)
#include <cuda_runtime.h>

// ---------------- problem constants ----------------
#define N_NODES 50000
#define N_EDGES 800000
#define ET (N_EDGES + N_NODES)      // 850000 edges incl. self loops
#define D_IN 128
#define HC1 128                     // layer1 heads*ch = 4*32
#define D_OUT 64                    // layer2, 1 head of 64
#define SCAN_T 1024
#define NB ((N_NODES + SCAN_T - 1) / SCAN_T)   // 49
#define GK 128                      // K is 128 for every GEMM in this net

typedef unsigned long long ull;

// ---------------- scratch (no allocs allowed) ----------------
__device__ float g_xl[N_NODES * HC1];
__device__ float g_xr[N_NODES * HC1];
__device__ float g_h [N_NODES * HC1];
__device__ int   g_counts[N_NODES];
__device__ int   g_cursor[N_NODES];
__device__ int   g_rowptr[N_NODES + 1];
__device__ int   g_col[ET];
__device__ int   g_bsums[NB];

__device__ __forceinline__ float leaky(float v) {
    return (v > 0.f) ? v : 0.2f * v;
}

// ---------------- CSR construction ----------------
__global__ void count_k(const int* __restrict__ dstv, int* __restrict__ counts) {
    int e = blockIdx.x * blockDim.x + threadIdx.x;
    if (e >= ET) return;
    int d = (e < N_EDGES) ? dstv[e] : (e - N_EDGES);
    atomicAdd(&counts[d], 1);
}

__global__ void scan_block_k(const int* __restrict__ in, int* __restrict__ out,
                             int* __restrict__ bsums, int n) {
    __shared__ int sm[SCAN_T];
    int t = threadIdx.x;
    int i = blockIdx.x * SCAN_T + t;
    int v = (i < n) ? in[i] : 0;
    sm[t] = v;
    __syncthreads();
    #pragma unroll
    for (int off = 1; off < SCAN_T; off <<= 1) {
        int x = (t >= off) ? sm[t - off] : 0;
        __syncthreads();
        sm[t] += x;
        __syncthreads();
    }
    if (i < n) out[i] = sm[t] - v;              // exclusive
    if (t == SCAN_T - 1) bsums[blockIdx.x] = sm[t];
}

__global__ void scan_sums_k(int* bsums) {       // NB <= 64
    __shared__ int sm[64];
    int t = threadIdx.x;
    int v = (t < NB) ? bsums[t] : 0;
    sm[t] = v;
    __syncthreads();
    #pragma unroll
    for (int off = 1; off < 64; off <<= 1) {
        int x = (t >= off) ? sm[t - off] : 0;
        __syncthreads();
        sm[t] += x;
        __syncthreads();
    }
    if (t < NB) bsums[t] = sm[t] - v;           // exclusive
}

__global__ void scan_add_k(int* __restrict__ out, const int* __restrict__ bsums,
                           int n, int total) {
    int i = blockIdx.x * SCAN_T + threadIdx.x;
    if (i < n) out[i] += bsums[blockIdx.x];
    if (i == n) out[n] = total;
}

__global__ void scatter_k(const int* __restrict__ srcv, const int* __restrict__ dstv,
                          const int* __restrict__ rowptr, int* __restrict__ cursor,
                          int* __restrict__ colv) {
    int e = blockIdx.x * blockDim.x + threadIdx.x;
    if (e >= ET) return;
    int d, s;
    if (e < N_EDGES) { d = dstv[e]; s = srcv[e]; }
    else             { d = s = e - N_EDGES; }
    int pos = rowptr[d] + atomicAdd(&cursor[d], 1);
    colv[pos] = s;
}

// ---------------- dual-output GEMM, f32x2 FMA ----------------
// C1 = A@B1 + bias1, C2 = A@B2 + bias2.  K fixed at 128, fully unrolled.
// R8 profile: L1(shared)=70.4% > fma=46.6% -> smem-bound from duplicated-A
// layout. Fix: store A natural float (8KB), 2xLDS.128 per k, duplicate into
// {v,v} pairs with ALU movs (alu pipe was 4% idle). ~33% fewer LDS wavefronts.
#define BM 128
#define BN 64
#define BK 16
#define TMR 8
#define TNR 4
#define NKT (GK / BK)   // 8 K-slabs

__global__ void __launch_bounds__(256, 2)
gemm_dual_k(const float* __restrict__ A,
            const float* __restrict__ B1, const float* __restrict__ bias1,
            const float* __restrict__ B2, const float* __restrict__ bias2,
            float* __restrict__ C1, float* __restrict__ C2,
            int M, int N) {
    __shared__ float As [BK][BM];   // 8 KB, natural layout
    __shared__ float Bs1[BK][BN];   // 4 KB
    __shared__ float Bs2[BK][BN];   // 4 KB

    int tx = threadIdx.x, ty = threadIdx.y;
    int tid = ty * 16 + tx;
    int row0 = blockIdx.y * BM;
    int col0 = blockIdx.x * BN;

    // A-staging coords: 2 chunks of float4 per thread
    int ar[2], ac[2], agr[2];
    #pragma unroll
    for (int it = 0; it < 2; it++) {
        int li = tid + it * 256;
        ar[it] = li >> 2;                       // 0..127
        ac[it] = (li & 3) << 2;                 // 0,4,8,12
        agr[it] = row0 + ar[it];
    }
    int br = tid >> 4;                          // 0..15
    int bc = (tid & 15) << 2;                   // 0..60

    ull acc1[TMR][TNR / 2];
    ull acc2[TMR][TNR / 2];
    #pragma unroll
    for (int m = 0; m < TMR; m++)
        #pragma unroll
        for (int n = 0; n < TNR / 2; n++) { acc1[m][n] = 0ULL; acc2[m][n] = 0ULL; }

    float4 va[2], vb1, vb2;

    // ---- prologue: fetch slab 0 ----
    #pragma unroll
    for (int it = 0; it < 2; it++) {
        va[it] = make_float4(0.f, 0.f, 0.f, 0.f);
        if (agr[it] < M) va[it] = *(const float4*)(A + (size_t)agr[it] * GK + ac[it]);
    }
    vb1 = *(const float4*)(B1 + (size_t)br * N + col0 + bc);
    vb2 = *(const float4*)(B2 + (size_t)br * N + col0 + bc);

    #pragma unroll
    for (int kt = 0; kt < NKT; kt++) {
        // store staged slab to smem (natural float layout)
        #pragma unroll
        for (int it = 0; it < 2; it++) {
            As[ac[it] + 0][ar[it]] = va[it].x;
            As[ac[it] + 1][ar[it]] = va[it].y;
            As[ac[it] + 2][ar[it]] = va[it].z;
            As[ac[it] + 3][ar[it]] = va[it].w;
        }
        Bs1[br][bc] = vb1.x; Bs1[br][bc + 1] = vb1.y;
        Bs1[br][bc + 2] = vb1.z; Bs1[br][bc + 3] = vb1.w;
        Bs2[br][bc] = vb2.x; Bs2[br][bc + 1] = vb2.y;
        Bs2[br][bc + 2] = vb2.z; Bs2[br][bc + 3] = vb2.w;
        __syncthreads();

        // prefetch next slab into registers (overlaps with compute below)
        if (kt + 1 < NKT) {
            int k0 = (kt + 1) * BK;
            #pragma unroll
            for (int it = 0; it < 2; it++)
                if (agr[it] < M) va[it] = *(const float4*)(A + (size_t)agr[it] * GK + k0 + ac[it]);
            vb1 = *(const float4*)(B1 + (size_t)(k0 + br) * N + col0 + bc);
            vb2 = *(const float4*)(B2 + (size_t)(k0 + br) * N + col0 + bc);
        }

        #pragma unroll
        for (int k = 0; k < BK; k++) {
            // A: 2 x LDS.128 (broadcast across 16 threads), then dup in-register
            float4 af0 = *(const float4*)&As[k][ty * TMR];
            float4 af1 = *(const float4*)&As[k][ty * TMR + 4];
            ull a2[TMR];
            asm("mov.b64 %0, {%1, %1};" : "=l"(a2[0]) : "f"(af0.x));
            asm("mov.b64 %0, {%1, %1};" : "=l"(a2[1]) : "f"(af0.y));
            asm("mov.b64 %0, {%1, %1};" : "=l"(a2[2]) : "f"(af0.z));
            asm("mov.b64 %0, {%1, %1};" : "=l"(a2[3]) : "f"(af0.w));
            asm("mov.b64 %0, {%1, %1};" : "=l"(a2[4]) : "f"(af1.x));
            asm("mov.b64 %0, {%1, %1};" : "=l"(a2[5]) : "f"(af1.y));
            asm("mov.b64 %0, {%1, %1};" : "=l"(a2[6]) : "f"(af1.z));
            asm("mov.b64 %0, {%1, %1};" : "=l"(a2[7]) : "f"(af1.w));
            ull rb1[2], rb2[2];
            rb1[0] = *(const ull*)&Bs1[k][tx * TNR];
            rb1[1] = *(const ull*)&Bs1[k][tx * TNR + 2];
            rb2[0] = *(const ull*)&Bs2[k][tx * TNR];
            rb2[1] = *(const ull*)&Bs2[k][tx * TNR + 2];
            #pragma unroll
            for (int m = 0; m < TMR; m++) {
                #pragma unroll
                for (int n = 0; n < TNR / 2; n++) {
                    asm("fma.rn.f32x2 %0, %1, %2, %0;"
                        : "+l"(acc1[m][n]) : "l"(a2[m]), "l"(rb1[n]));
                    asm("fma.rn.f32x2 %0, %1, %2, %0;"
                        : "+l"(acc2[m][n]) : "l"(a2[m]), "l"(rb2[n]));
                }
            }
        }
        __syncthreads();
    }

    #pragma unroll
    for (int m = 0; m < TMR; m++) {
        int gr = row0 + ty * TMR + m;
        if (gr >= M) continue;
        #pragma unroll
        for (int n = 0; n < TNR / 2; n++) {
            int gc = col0 + tx * TNR + n * 2;
            float lo, hi;
            asm("mov.b64 {%0, %1}, %2;" : "=f"(lo), "=f"(hi) : "l"(acc1[m][n]));
            *(float2*)(C1 + (size_t)gr * N + gc) =
                make_float2(lo + bias1[gc], hi + bias1[gc + 1]);
            asm("mov.b64 {%0, %1}, %2;" : "=f"(lo), "=f"(hi) : "l"(acc2[m][n]));
            *(float2*)(C2 + (size_t)gr * N + gc) =
                make_float2(lo + bias2[gc], hi + bias2[gc + 1]);
        }
    }
}

// ---------------- fused GATv2 attention+aggregation ----------------
// Layer 1: warp per node. lane = 4 channels (float4); 8 lanes per head;
// warp covers all 4 heads. Per edge: 1 LDG.128/lane, 3-level shuffle tree
// (within 8-lane head groups), ONE __expf serving all 4 heads, fp32 fma acc.
// 2-edge unroll for ILP. (softmax max-shift dropped: scores are O(1))
__global__ void __launch_bounds__(256)
attn_l1_k(const float* __restrict__ xl, const float* __restrict__ xr,
          const float* __restrict__ att, const float* __restrict__ bias,
          const int* __restrict__ rowptr, const int* __restrict__ colv,
          float* __restrict__ out) {
    int node = (blockIdx.x * blockDim.x + threadIdx.x) >> 5;
    if (node >= N_NODES) return;
    int lane = threadIdx.x & 31;
    int c4 = lane * 4;                          // channel base (head = lane>>3)
    float4 a4  = *(const float4*)(att + c4);
    float4 xr4 = *(const float4*)(xr + (size_t)node * HC1 + c4);
    int beg = rowptr[node], end = rowptr[node + 1];
    float4 acc = make_float4(0.f, 0.f, 0.f, 0.f);
    float denom = 0.f;
    int idx = beg;
    for (; idx + 2 <= end; idx += 2) {
        int j0 = colv[idx], j1 = colv[idx + 1];
        float4 m0 = __ldg((const float4*)(xl + (size_t)j0 * HC1 + c4));
        float4 m1 = __ldg((const float4*)(xl + (size_t)j1 * HC1 + c4));
        float s0 = leaky(m0.x + xr4.x) * a4.x;
        s0 = fmaf(leaky(m0.y + xr4.y), a4.y, s0);
        s0 = fmaf(leaky(m0.z + xr4.z), a4.z, s0);
        s0 = fmaf(leaky(m0.w + xr4.w), a4.w, s0);
        float s1 = leaky(m1.x + xr4.x) * a4.x;
        s1 = fmaf(leaky(m1.y + xr4.y), a4.y, s1);
        s1 = fmaf(leaky(m1.z + xr4.z), a4.z, s1);
        s1 = fmaf(leaky(m1.w + xr4.w), a4.w, s1);
        #pragma unroll
        for (int o = 4; o; o >>= 1) {           // sum within 8-lane head group
            s0 += __shfl_xor_sync(0xffffffffu, s0, o);
            s1 += __shfl_xor_sync(0xffffffffu, s1, o);
        }
        float x0 = __expf(s0), x1 = __expf(s1); // per-lane: own head's score
        denom += x0 + x1;
        acc.x = fmaf(x0, m0.x, acc.x); acc.y = fmaf(x0, m0.y, acc.y);
        acc.z = fmaf(x0, m0.z, acc.z); acc.w = fmaf(x0, m0.w, acc.w);
        acc.x = fmaf(x1, m1.x, acc.x); acc.y = fmaf(x1, m1.y, acc.y);
        acc.z = fmaf(x1, m1.z, acc.z); acc.w = fmaf(x1, m1.w, acc.w);
    }
    if (idx < end) {
        int j = colv[idx];
        float4 m = __ldg((const float4*)(xl + (size_t)j * HC1 + c4));
        float s = leaky(m.x + xr4.x) * a4.x;
        s = fmaf(leaky(m.y + xr4.y), a4.y, s);
        s = fmaf(leaky(m.z + xr4.z), a4.z, s);
        s = fmaf(leaky(m.w + xr4.w), a4.w, s);
        #pragma unroll
        for (int o = 4; o; o >>= 1) s += __shfl_xor_sync(0xffffffffu, s, o);
        float ex = __expf(s);
        denom += ex;
        acc.x = fmaf(ex, m.x, acc.x); acc.y = fmaf(ex, m.y, acc.y);
        acc.z = fmaf(ex, m.z, acc.z); acc.w = fmaf(ex, m.w, acc.w);
    }
    float inv = 1.f / denom;                    // denom uniform within head group
    float4 b4 = *(const float4*)(bias + c4);
    float4 o4;
    o4.x = fmaxf(fmaf(acc.x, inv, b4.x), 0.f);
    o4.y = fmaxf(fmaf(acc.y, inv, b4.y), 0.f);
    o4.z = fmaxf(fmaf(acc.z, inv, b4.z), 0.f);
    o4.w = fmaxf(fmaf(acc.w, inv, b4.w), 0.f);
    *(float4*)(out + (size_t)node * HC1 + c4) = o4;     // fused ReLU
}

// Layer 2: warp per node, 1 head x 64 ch. 16 lanes x float4 = 64 ch; the two
// half-warps process two consecutive edges simultaneously (4-level tree within
// 16 lanes, one __expf per edge pair). Halves combined at the end via xor-16.
__global__ void __launch_bounds__(256)
attn_l2_k(const float* __restrict__ xl, const float* __restrict__ xr,
          const float* __restrict__ att, const float* __restrict__ bias,
          const int* __restrict__ rowptr, const int* __restrict__ colv,
          float* __restrict__ out) {
    int node = (blockIdx.x * blockDim.x + threadIdx.x) >> 5;
    if (node >= N_NODES) return;
    int lane = threadIdx.x & 31;
    int half = lane >> 4;                       // which edge of the pair
    int sl   = lane & 15;
    int c4   = sl * 4;                          // channel base
    float4 a4  = *(const float4*)(att + c4);
    float4 xr4 = *(const float4*)(xr + (size_t)node * D_OUT + c4);
    int beg = rowptr[node], end = rowptr[node + 1];
    float4 acc = make_float4(0.f, 0.f, 0.f, 0.f);
    float denom = 0.f;
    for (int idx = beg; idx < end; idx += 2) {
        int e = idx + half;
        bool valid = (e < end);
        int j = colv[valid ? e : (end - 1)];
        float4 m = __ldg((const float4*)(xl + (size_t)j * D_OUT + c4));
        float s = leaky(m.x + xr4.x) * a4.x;
        s = fmaf(leaky(m.y + xr4.y), a4.y, s);
        s = fmaf(leaky(m.z + xr4.z), a4.z, s);
        s = fmaf(leaky(m.w + xr4.w), a4.w, s);
        #pragma unroll
        for (int o = 8; o; o >>= 1) s += __shfl_xor_sync(0xffffffffu, s, o);
        float ex = valid ? __expf(s) : 0.f;
        denom += ex;
        acc.x = fmaf(ex, m.x, acc.x); acc.y = fmaf(ex, m.y, acc.y);
        acc.z = fmaf(ex, m.z, acc.z); acc.w = fmaf(ex, m.w, acc.w);
    }
    // combine the two half-warps
    denom += __shfl_xor_sync(0xffffffffu, denom, 16);
    acc.x += __shfl_xor_sync(0xffffffffu, acc.x, 16);
    acc.y += __shfl_xor_sync(0xffffffffu, acc.y, 16);
    acc.z += __shfl_xor_sync(0xffffffffu, acc.z, 16);
    acc.w += __shfl_xor_sync(0xffffffffu, acc.w, 16);
    if (half == 0) {
        float inv = 1.f / denom;
        float4 b4 = *(const float4*)(bias + c4);
        float4 o4;
        o4.x = fmaf(acc.x, inv, b4.x);
        o4.y = fmaf(acc.y, inv, b4.y);
        o4.z = fmaf(acc.z, inv, b4.z);
        o4.w = fmaf(acc.w, inv, b4.w);
        *(float4*)(out + (size_t)node * D_OUT + c4) = o4;
    }
}

// ---------------- host launcher ----------------
extern "C" void kernel_launch(void* const* d_in, const int* in_sizes, int n_in,
                              void* d_out, int out_size) {
    const float* x     = (const float*)d_in[0];
    const int*   ei    = (const int*)  d_in[1];
    const float* Wl1   = (const float*)d_in[2];
    const float* bl1   = (const float*)d_in[3];
    const float* Wr1   = (const float*)d_in[4];
    const float* br1   = (const float*)d_in[5];
    const float* att1  = (const float*)d_in[6];
    const float* bias1 = (const float*)d_in[7];
    const float* Wl2   = (const float*)d_in[8];
    const float* bl2   = (const float*)d_in[9];
    const float* Wr2   = (const float*)d_in[10];
    const float* br2   = (const float*)d_in[11];
    const float* att2  = (const float*)d_in[12];
    const float* bias2 = (const float*)d_in[13];
    float* out = (float*)d_out;

    float *xl, *xr, *h;
    int *counts, *cursor, *rowptr, *colv, *bsums;
    cudaGetSymbolAddress((void**)&xl,     g_xl);
    cudaGetSymbolAddress((void**)&xr,     g_xr);
    cudaGetSymbolAddress((void**)&h,      g_h);
    cudaGetSymbolAddress((void**)&counts, g_counts);
    cudaGetSymbolAddress((void**)&cursor, g_cursor);
    cudaGetSymbolAddress((void**)&rowptr, g_rowptr);
    cudaGetSymbolAddress((void**)&colv,   g_col);
    cudaGetSymbolAddress((void**)&bsums,  g_bsums);

    const int* srcv = ei;
    const int* dstv = ei + N_EDGES;

    dim3 blk(16, 16);
    dim3 g1(HC1 / BN,   (N_NODES + BM - 1) / BM);
    dim3 g2(D_OUT / BN, (N_NODES + BM - 1) / BM);
    int attn_blocks = (N_NODES * 32 + 255) / 256;   // warp per node

    // gemm_dual layer1 stays at kernel-launch index 3 (ncu capture window).
    cudaMemsetAsync(counts, 0, N_NODES * sizeof(int));
    cudaMemsetAsync(cursor, 0, N_NODES * sizeof(int));
    count_k     <<<(ET + 255) / 256, 256>>>(dstv, counts);                     // 0
    scan_block_k<<<NB, SCAN_T>>>(counts, rowptr, bsums, N_NODES);              // 1
    scan_sums_k <<<1, 64>>>(bsums);                                            // 2
    gemm_dual_k <<<g1, blk>>>(x, Wl1, bl1, Wr1, br1, xl, xr, N_NODES, HC1);    // 3
    scan_add_k  <<<NB, SCAN_T>>>(rowptr, bsums, N_NODES, ET);                  // 4
    scatter_k   <<<(ET + 255) / 256, 256>>>(srcv, dstv, rowptr, cursor, colv); // 5
    attn_l1_k   <<<attn_blocks, 256>>>(xl, xr, att1, bias1, rowptr, colv, h);  // 6
    gemm_dual_k <<<g2, blk>>>(h, Wl2, bl2, Wr2, br2, xl, xr, N_NODES, D_OUT);  // 7
    attn_l2_k   <<<attn_blocks, 256>>>(xl, xr, att2, bias2, rowptr, colv, out);// 8
}